// round 16
// baseline (speedup 1.0000x reference)
#include <cuda_runtime.h>
#include <cstdint>

#define BATCH 4
#define SEQ   8192
#define DM    1024
#define DK    128
#define NB    (BATCH*SEQ)   // 32768 total rows
#define NSLICE 8            // split-n slices for k_m
#define PADW  136           // [k][row] smem stride (k_m tiles)
#define PADK  20            // [row][k] smem stride (k_qk / k_out tiles)

// Scratch (device globals -- no dynamic allocation allowed)
__device__ float g_Q [(size_t)NB * DK];                    // 16 MB
__device__ float g_K [(size_t)NB * DK];                    // 16 MB
__device__ float g_Mp[(size_t)BATCH * NSLICE * DK * DM];   // 16 MB  [b,s][k][d]
__device__ float g_M [(size_t)BATCH * DM * DK];            // 2 MB   [b][d][k] (rounded)
__device__ float g_Jn[(size_t)NB * DM];                    // 128 MB

static __device__ __forceinline__ float tf32r(float x) {
    float y; asm("cvt.rna.tf32.f32 %0, %1;" : "=f"(y) : "f"(x)); return y;
}
static __device__ __forceinline__ float4 tf32r4(float4 v) {
    return make_float4(tf32r(v.x), tf32r(v.y), tf32r(v.z), tf32r(v.w));
}

#define MMA1(accv, a0_, a1_, a2_, a3_, b0_, b1_) \
    asm volatile( \
        "mma.sync.aligned.m16n8k8.row.col.f32.tf32.tf32.f32 " \
        "{%0,%1,%2,%3}, {%4,%5,%6,%7}, {%8,%9}, {%0,%1,%2,%3};" \
        : "+f"(accv[0]), "+f"(accv[1]), "+f"(accv[2]), "+f"(accv[3]) \
        : "r"(a0_), "r"(a1_), "r"(a2_), "r"(a3_), "r"(b0_), "r"(b1_))

// 8-k microstep, [row][k] PADK layout: As_[.][PADK], Bs_[.][PADK]
// warp tile 64(m) x 32(n) -> acc[4][4][4]. Conflict-free frag loads.
#define MMA_RK(As_, Bs_, ks_) do {                                              \
    uint32_t afr[4][4], bfr[4][2];                                              \
    _Pragma("unroll")                                                           \
    for (int im = 0; im < 4; im++) {                                            \
        afr[im][0] = *(const uint32_t*)&As_[am + im*16    ][(ks_) + tg    ];    \
        afr[im][1] = *(const uint32_t*)&As_[am + im*16 + 8][(ks_) + tg    ];    \
        afr[im][2] = *(const uint32_t*)&As_[am + im*16    ][(ks_) + tg + 4];    \
        afr[im][3] = *(const uint32_t*)&As_[am + im*16 + 8][(ks_) + tg + 4];    \
    }                                                                           \
    _Pragma("unroll")                                                           \
    for (int jn = 0; jn < 4; jn++) {                                            \
        bfr[jn][0] = *(const uint32_t*)&Bs_[bn + jn*8][(ks_) + tg    ];         \
        bfr[jn][1] = *(const uint32_t*)&Bs_[bn + jn*8][(ks_) + tg + 4];         \
    }                                                                           \
    _Pragma("unroll")                                                           \
    for (int im = 0; im < 4; im++)                                              \
    _Pragma("unroll")                                                           \
    for (int jn = 0; jn < 4; jn++)                                              \
        MMA1(acc[im][jn], afr[im][0], afr[im][1], afr[im][2], afr[im][3],       \
             bfr[jn][0], bfr[jn][1]);                                           \
} while (0)

// 8-k microstep, [k][row] PADW layout (k_m): As_[16][PADW], Bs_[16][PADW]
#define MMA_KR(As_, Bs_, ks_) do {                                              \
    uint32_t afr[4][4], bfr[4][2];                                              \
    _Pragma("unroll")                                                           \
    for (int im = 0; im < 4; im++) {                                            \
        const uint32_t* p0 = (const uint32_t*)&As_[(ks_) + tg    ][am + im*16]; \
        const uint32_t* p1 = (const uint32_t*)&As_[(ks_) + tg + 4][am + im*16]; \
        afr[im][0] = p0[0]; afr[im][1] = p0[8];                                 \
        afr[im][2] = p1[0]; afr[im][3] = p1[8];                                 \
    }                                                                           \
    _Pragma("unroll")                                                           \
    for (int jn = 0; jn < 4; jn++) {                                            \
        bfr[jn][0] = *(const uint32_t*)&Bs_[(ks_) + tg    ][bn + jn * 8];       \
        bfr[jn][1] = *(const uint32_t*)&Bs_[(ks_) + tg + 4][bn + jn * 8];       \
    }                                                                           \
    _Pragma("unroll")                                                           \
    for (int im = 0; im < 4; im++)                                              \
    _Pragma("unroll")                                                           \
    for (int jn = 0; jn < 4; jn++)                                              \
        MMA1(acc[im][jn], afr[im][0], afr[im][1], afr[im][2], afr[im][3],       \
             bfr[jn][0], bfr[jn][1]);                                           \
} while (0)

#define WARP_IDX()                                                              \
    const int lane = t & 31;                                                    \
    const int w  = t >> 5;                                                      \
    const int wm = w & 1;                                                       \
    const int wn = w >> 1;                                                      \
    const int g  = lane >> 2;                                                   \
    const int tg = lane & 3;                                                    \
    const int am = wm * 64 + g;                                                 \
    const int bn = wn * 32 + g;

// ---------------------------------------------------------------------------
// Kernel 1: Q|K projection. C[m][j] = sum_d J[m][d] * W[j][d]
// blockIdx.y == 0 -> W_Q / g_Q ; == 1 -> W_K / g_K.
// [row][k] PADK layout, BK=16, double-buffered, vector float4 staging.
// ---------------------------------------------------------------------------
__global__ void __launch_bounds__(256, 2) k_qk(const float* __restrict__ J,
                                               const float* __restrict__ WQ,
                                               const float* __restrict__ WK) {
    __shared__ float As[2][128][PADK];   // [buf][m][k]
    __shared__ float Bs[2][128][PADK];   // [buf][j][k]
    const int t  = threadIdx.x;
    const int m0 = blockIdx.x * 128;
    const float* W = (blockIdx.y == 0) ? WQ : WK;
    float* OUT     = (blockIdx.y == 0) ? g_Q : g_K;

    const int row = t >> 1;           // 0..127
    const int q   = t & 1;            // which 8-float half of the 16-k chunk
    WARP_IDX();

    const float* aR = J + (size_t)(m0 + row) * DM + q * 8;
    const float* wR = W + (size_t)row * DM + q * 8;

    {   // prologue: tile 0 -> buf 0
        *(float4*)&As[0][row][q * 8]     = tf32r4(*(const float4*)(aR));
        *(float4*)&As[0][row][q * 8 + 4] = tf32r4(*(const float4*)(aR + 4));
        *(float4*)&Bs[0][row][q * 8]     = tf32r4(*(const float4*)(wR));
        *(float4*)&Bs[0][row][q * 8 + 4] = tf32r4(*(const float4*)(wR + 4));
    }
    __syncthreads();

    float acc[4][4][4] = {};
    int buf = 0;
    for (int k0 = 0; k0 < DM; k0 += 16) {
        const bool hn = (k0 + 16) < DM;
        const int nx = buf ^ 1;
        float4 na0, na1;
        if (hn) {
            na0 = *(const float4*)(aR + k0 + 16);
            na1 = *(const float4*)(aR + k0 + 20);
        }
        MMA_RK(As[buf], Bs[buf], 0);
        float4 nb0, nb1;
        if (hn) {
            *(float4*)&As[nx][row][q * 8]     = tf32r4(na0);
            *(float4*)&As[nx][row][q * 8 + 4] = tf32r4(na1);
            nb0 = *(const float4*)(wR + k0 + 16);
            nb1 = *(const float4*)(wR + k0 + 20);
        }
        MMA_RK(As[buf], Bs[buf], 8);
        if (hn) {
            *(float4*)&Bs[nx][row][q * 8]     = tf32r4(nb0);
            *(float4*)&Bs[nx][row][q * 8 + 4] = tf32r4(nb1);
        }
        __syncthreads();
        buf = nx;
    }
#pragma unroll
    for (int im = 0; im < 4; im++)
#pragma unroll
    for (int jn = 0; jn < 4; jn++) {
        const size_t m = (size_t)(m0 + wm * 64 + im * 16 + g);
        const int    c = wn * 32 + jn * 8 + 2 * tg;
        *(float2*)(OUT + m * DK + c)       = make_float2(acc[im][jn][0], acc[im][jn][1]);
        *(float2*)(OUT + (m + 8) * DK + c) = make_float2(acc[im][jn][2], acc[im][jn][3]);
    }
}

// ---------------------------------------------------------------------------
// Kernel 2: partial M. Mp[b][s][k][d] = sum_{n in slice s} K[b][n][k]*J[b][n][d]
// grid: (DM/128, NSLICE, BATCH); tile 128(k) x 128(d), n-chunk 16, KR layout.
// ---------------------------------------------------------------------------
__global__ void __launch_bounds__(256, 2) k_m(const float* __restrict__ J) {
    __shared__ float Ks[2][16][PADW];   // [buf][n][k]
    __shared__ float Js[2][16][PADW];   // [buf][n][d]
    const int t  = threadIdx.x;
    const int d0 = blockIdx.x * 128;
    const int s  = blockIdx.y;
    const int b  = blockIdx.z;

    const int ln = t >> 5;            // 0..7 (covers rows ln, ln+8)
    const int lc = (t & 31) << 2;     // 0..124
    WARP_IDX();

    const int nbeg = s * (SEQ / NSLICE);
    const int nend = nbeg + (SEQ / NSLICE);
    const float* Kb = g_K + (size_t)b * SEQ * DK + lc;
    const float* Jb = J   + (size_t)b * SEQ * DM + d0 + lc;

    {   // prologue
        *(float4*)&Ks[0][ln    ][lc] = tf32r4(*(const float4*)(Kb + (size_t)(nbeg + ln    ) * DK));
        *(float4*)&Ks[0][ln + 8][lc] = tf32r4(*(const float4*)(Kb + (size_t)(nbeg + ln + 8) * DK));
        *(float4*)&Js[0][ln    ][lc] = tf32r4(*(const float4*)(Jb + (size_t)(nbeg + ln    ) * DM));
        *(float4*)&Js[0][ln + 8][lc] = tf32r4(*(const float4*)(Jb + (size_t)(nbeg + ln + 8) * DM));
    }
    __syncthreads();

    float acc[4][4][4] = {};
    int buf = 0;
    for (int n0 = nbeg; n0 < nend; n0 += 16) {
        const bool hn = (n0 + 16) < nend;
        const int nx = buf ^ 1;
        float4 nk0, nk1;
        if (hn) {
            nk0 = *(const float4*)(Kb + (size_t)(n0 + 16 + ln    ) * DK);
            nk1 = *(const float4*)(Kb + (size_t)(n0 + 16 + ln + 8) * DK);
        }
        MMA_KR(Ks[buf], Js[buf], 0);
        float4 nj0, nj1;
        if (hn) {
            *(float4*)&Ks[nx][ln    ][lc] = tf32r4(nk0);
            *(float4*)&Ks[nx][ln + 8][lc] = tf32r4(nk1);
            nj0 = *(const float4*)(Jb + (size_t)(n0 + 16 + ln    ) * DM);
            nj1 = *(const float4*)(Jb + (size_t)(n0 + 16 + ln + 8) * DM);
        }
        MMA_KR(Ks[buf], Js[buf], 8);
        if (hn) {
            *(float4*)&Js[nx][ln    ][lc] = tf32r4(nj0);
            *(float4*)&Js[nx][ln + 8][lc] = tf32r4(nj1);
        }
        __syncthreads();
        buf = nx;
    }
    float* Mp = g_Mp + ((size_t)(b * NSLICE + s) * DK) * DM;
#pragma unroll
    for (int im = 0; im < 4; im++)
#pragma unroll
    for (int jn = 0; jn < 4; jn++) {
        const int k = wm * 64 + im * 16 + g;
        const int c = d0 + wn * 32 + jn * 8 + 2 * tg;
        *(float2*)(Mp + (size_t)k * DM + c)       = make_float2(acc[im][jn][0], acc[im][jn][1]);
        *(float2*)(Mp + (size_t)(k + 8) * DM + c) = make_float2(acc[im][jn][2], acc[im][jn][3]);
    }
}

// ---------------------------------------------------------------------------
// Kernel 2b: reduce slices + transpose + round: g_M[b][d][k] = tf32r(sum_s Mp)
// grid (DK/32, DM/32, BATCH), block (32,8)
// ---------------------------------------------------------------------------
__global__ void __launch_bounds__(256) k_mred() {
    __shared__ float tl[32][33];
    const int tx = threadIdx.x, ty = threadIdx.y;
    const int k0 = blockIdx.x * 32, d0 = blockIdx.y * 32, b = blockIdx.z;
#pragma unroll
    for (int i = 0; i < 4; i++) {
        float s = 0.f;
#pragma unroll
        for (int sl = 0; sl < NSLICE; sl++)
            s += g_Mp[((size_t)(b * NSLICE + sl) * DK + k0 + ty + i * 8) * DM + d0 + tx];
        tl[ty + i * 8][tx] = tf32r(s);  // tl[k_local][d_local]
    }
    __syncthreads();
#pragma unroll
    for (int i = 0; i < 4; i++)
        g_M[((size_t)b * DM + d0 + ty + i * 8) * DK + k0 + tx] = tl[tx][ty + i * 8];
}

// ---------------------------------------------------------------------------
// Kernel 3: J_new[m][d] = sc * sum_k Q[m][k]*M[b][d][k] + J[m][d]
// 128(m) x 64(d) tile, 128 threads (4 warps 2m x 2n), 4 CTAs/SM ->
// 4 independent barrier domains per SM (desynchronized pipelines).
// [row][k] PADK layout, BK=16 -> 8 iters. grid (NB/128, DM/64).
// ---------------------------------------------------------------------------
__global__ void __launch_bounds__(128, 4) k_out(const float* __restrict__ J) {
    __shared__ float As[2][128][PADK];   // [buf][m][k]  (Q tile)
    __shared__ float Bs[2][64][PADK];    // [buf][d][k]  (M tile)
    const int t  = threadIdx.x;
    const int m0 = blockIdx.x * 128;
    const int d0 = blockIdx.y * 64;
    const int bb = blockIdx.x >> 6;      // m0 / SEQ

    WARP_IDX();                          // wm=w&1 (2 m-warps), wn=w>>1 (2 n-warps)

    // A staging: 1 thread per row, 4 float4 (16 k floats)
    const float* aR = g_Q + (size_t)(m0 + t) * DK;
    // B staging: 2 threads per row, 2 float4 each
    const int brow = t >> 1, bq = t & 1;
    const float* bR = g_M + ((size_t)bb * DM + d0 + brow) * DK + bq * 8;

    {   // prologue (M already tf32-rounded by k_mred)
        *(float4*)&As[0][t][0]  = tf32r4(*(const float4*)(aR));
        *(float4*)&As[0][t][4]  = tf32r4(*(const float4*)(aR + 4));
        *(float4*)&As[0][t][8]  = tf32r4(*(const float4*)(aR + 8));
        *(float4*)&As[0][t][12] = tf32r4(*(const float4*)(aR + 12));
        *(float4*)&Bs[0][brow][bq * 8]     = *(const float4*)(bR);
        *(float4*)&Bs[0][brow][bq * 8 + 4] = *(const float4*)(bR + 4);
    }
    __syncthreads();

    float acc[4][4][4] = {};
    int buf = 0;
    for (int k0 = 0; k0 < DK; k0 += 16) {
        const bool hn = (k0 + 16) < DK;
        const int nx = buf ^ 1;
        float4 na0, na1, na2, na3;
        if (hn) {
            na0 = *(const float4*)(aR + k0 + 16);
            na1 = *(const float4*)(aR + k0 + 20);
            na2 = *(const float4*)(aR + k0 + 24);
            na3 = *(const float4*)(aR + k0 + 28);
        }
        MMA_RK(As[buf], Bs[buf], 0);
        float4 nb0, nb1;
        if (hn) {
            *(float4*)&As[nx][t][0]  = tf32r4(na0);
            *(float4*)&As[nx][t][4]  = tf32r4(na1);
            *(float4*)&As[nx][t][8]  = tf32r4(na2);
            *(float4*)&As[nx][t][12] = tf32r4(na3);
            nb0 = *(const float4*)(bR + k0 + 16);
            nb1 = *(const float4*)(bR + k0 + 20);
        }
        MMA_RK(As[buf], Bs[buf], 8);
        if (hn) {
            *(float4*)&Bs[nx][brow][bq * 8]     = nb0;
            *(float4*)&Bs[nx][brow][bq * 8 + 4] = nb1;
        }
        __syncthreads();
        buf = nx;
    }
    const float sc = 0.088388347648318447f;  // 1/sqrt(128)
#pragma unroll
    for (int im = 0; im < 4; im++)
#pragma unroll
    for (int jn = 0; jn < 4; jn++) {
        const size_t m  = (size_t)(m0 + wm * 64 + im * 16 + g);
        const int    dd = d0 + wn * 32 + jn * 8 + 2 * tg;
        float2 j0 = *(const float2*)(J + m * DM + dd);
        float2 j1 = *(const float2*)(J + (m + 8) * DM + dd);
        *(float2*)(g_Jn + m * DM + dd) =
            make_float2(acc[im][jn][0] * sc + j0.x, acc[im][jn][1] * sc + j0.y);
        *(float2*)(g_Jn + (m + 8) * DM + dd) =
            make_float2(acc[im][jn][2] * sc + j1.x, acc[im][jn][3] * sc + j1.y);
    }
}

// ---------------------------------------------------------------------------
// Kernel 4: LayerNorm over last dim (1024). One block (256 thr) per row.
// ---------------------------------------------------------------------------
__global__ void __launch_bounds__(256) k_ln(const float* __restrict__ gamma,
                                            const float* __restrict__ beta,
                                            float* __restrict__ out) {
    __shared__ float sred[8], ssred[8];
    const int t = threadIdx.x;
    const size_t row = blockIdx.x;
    const int dd = t << 2;

    float4 v = *(const float4*)(g_Jn + row * DM + dd);
    float s  = v.x + v.y + v.z + v.w;
    float ss = v.x * v.x + v.y * v.y + v.z * v.z + v.w * v.w;
#pragma unroll
    for (int o = 16; o > 0; o >>= 1) {
        s  += __shfl_xor_sync(0xffffffffu, s,  o);
        ss += __shfl_xor_sync(0xffffffffu, ss, o);
    }
    const int w = t >> 5;
    if ((t & 31) == 0) { sred[w] = s; ssred[w] = ss; }
    __syncthreads();
    s = 0.f; ss = 0.f;
#pragma unroll
    for (int i = 0; i < 8; i++) { s += sred[i]; ss += ssred[i]; }

    const float mean = s * (1.0f / DM);
    const float var  = ss * (1.0f / DM) - mean * mean;
    const float rstd = rsqrtf(var + 1e-5f);

    float4 g = *(const float4*)(gamma + dd);
    float4 b = *(const float4*)(beta + dd);
    float4 o;
    o.x = (v.x - mean) * rstd * g.x + b.x;
    o.y = (v.y - mean) * rstd * g.y + b.y;
    o.z = (v.z - mean) * rstd * g.z + b.z;
    o.w = (v.w - mean) * rstd * g.w + b.w;
    *(float4*)(out + row * DM + dd) = o;
}

// ---------------------------------------------------------------------------
extern "C" void kernel_launch(void* const* d_in, const int* in_sizes, int n_in,
                              void* d_out, int out_size) {
    (void)in_sizes; (void)n_in; (void)out_size;
    const float* J     = (const float*)d_in[0];
    const float* WQ    = (const float*)d_in[1];
    const float* WK    = (const float*)d_in[2];
    const float* gamma = (const float*)d_in[3];
    const float* beta  = (const float*)d_in[4];
    float* out = (float*)d_out;

    k_qk  <<<dim3(NB / 128, 2), 256>>>(J, WQ, WK);
    k_m   <<<dim3(DM / 128, NSLICE, BATCH), 256>>>(J);
    k_mred<<<dim3(DK / 32, DM / 32, BATCH), dim3(32, 8)>>>();
    k_out <<<dim3(NB / 128, DM / 64), 128>>>(J);
    k_ln  <<<NB, 256>>>(gamma, beta, out);
}